// round 1
// baseline (speedup 1.0000x reference)
#include <cuda_runtime.h>
#include <cuda_bf16.h>
#include <cstdint>

#define GN 2048
#define GD 512
#define GB 8
#define NEG_INF_F (-9999999.0f)

// 8 * 2048 * 2048 floats = 134 MB scratch for the score / probability matrix.
__device__ float g_scratch[(size_t)GB * GN * GN];

// ---------------------------------------------------------------------------
// Kernel 1: S[b,n,m] = sum_d X[b,n,d] * X[b,m,d], masked to NEG_INF where
// (adj[b,n,m] == 0 && n != m).  NT GEMM, 128x128 tile, BK=16, 8x8 per thread.
// ---------------------------------------------------------------------------
__global__ __launch_bounds__(256) void gemm_scores(const float* __restrict__ X,
                                                   const int* __restrict__ adj) {
    const int b = blockIdx.z;
    const int rowBase = blockIdx.y * 128;
    const int colBase = blockIdx.x * 128;
    const float* Xb = X + (size_t)b * GN * GD;

    __shared__ float As[16][128];
    __shared__ float Bs[16][128];

    float acc[8][8] = {};

    const int tid = threadIdx.x;
    const int tx = tid & 15;    // 0..15 -> col micro-tile
    const int ty = tid >> 4;    // 0..15 -> row micro-tile

    for (int d0 = 0; d0 < GD; d0 += 16) {
        // Load A tile (128 rows x 16 k) and B tile (128 cols x 16 k),
        // stored transposed: As[k][row], Bs[k][col].
#pragma unroll
        for (int l = 0; l < 2; l++) {
            int slot = tid + l * 256;          // 0..511
            int row  = slot >> 2;              // 0..127
            int k4   = (slot & 3) << 2;        // 0,4,8,12
            float4 va = *(const float4*)(Xb + (size_t)(rowBase + row) * GD + d0 + k4);
            As[k4 + 0][row] = va.x;
            As[k4 + 1][row] = va.y;
            As[k4 + 2][row] = va.z;
            As[k4 + 3][row] = va.w;
            float4 vb = *(const float4*)(Xb + (size_t)(colBase + row) * GD + d0 + k4);
            Bs[k4 + 0][row] = vb.x;
            Bs[k4 + 1][row] = vb.y;
            Bs[k4 + 2][row] = vb.z;
            Bs[k4 + 3][row] = vb.w;
        }
        __syncthreads();

#pragma unroll
        for (int k = 0; k < 16; k++) {
            float4 a0 = *(const float4*)&As[k][ty * 8];
            float4 a1 = *(const float4*)&As[k][ty * 8 + 4];
            float4 b0 = *(const float4*)&Bs[k][tx * 8];
            float4 b1 = *(const float4*)&Bs[k][tx * 8 + 4];
            float a[8] = {a0.x, a0.y, a0.z, a0.w, a1.x, a1.y, a1.z, a1.w};
            float bb[8] = {b0.x, b0.y, b0.z, b0.w, b1.x, b1.y, b1.z, b1.w};
#pragma unroll
            for (int i = 0; i < 8; i++)
#pragma unroll
                for (int j = 0; j < 8; j++)
                    acc[i][j] = fmaf(a[i], bb[j], acc[i][j]);
        }
        __syncthreads();
    }

    // Epilogue: mask with adjacency (+ self loop) and store to scratch.
    const int* adjb = adj + (size_t)b * GN * GN;
    float* Sb = g_scratch + (size_t)b * GN * GN;
#pragma unroll
    for (int i = 0; i < 8; i++) {
        const int n = rowBase + ty * 8 + i;
        const int m0 = colBase + tx * 8;
        int4 m4a = *(const int4*)(adjb + (size_t)n * GN + m0);
        int4 m4b = *(const int4*)(adjb + (size_t)n * GN + m0 + 4);
        float v[8];
        int mk[8] = {m4a.x, m4a.y, m4a.z, m4a.w, m4b.x, m4b.y, m4b.z, m4b.w};
#pragma unroll
        for (int j = 0; j < 8; j++) {
            bool keep = (mk[j] != 0) || (n == (m0 + j));
            v[j] = keep ? acc[i][j] : NEG_INF_F;
        }
        *(float4*)(Sb + (size_t)n * GN + m0)     = make_float4(v[0], v[1], v[2], v[3]);
        *(float4*)(Sb + (size_t)n * GN + m0 + 4) = make_float4(v[4], v[5], v[6], v[7]);
    }
}

// ---------------------------------------------------------------------------
// Kernel 2: in-place row softmax over g_scratch. One CTA (256 thr) per row.
// ---------------------------------------------------------------------------
__device__ __forceinline__ float warpMax(float v) {
#pragma unroll
    for (int o = 16; o > 0; o >>= 1) v = fmaxf(v, __shfl_xor_sync(0xffffffffu, v, o));
    return v;
}
__device__ __forceinline__ float warpSum(float v) {
#pragma unroll
    for (int o = 16; o > 0; o >>= 1) v += __shfl_xor_sync(0xffffffffu, v, o);
    return v;
}

__global__ __launch_bounds__(256) void softmax_rows() {
    __shared__ float red[8];
    float* p = g_scratch + (size_t)blockIdx.x * GN;
    const int tid = threadIdx.x;

    float4 v0 = ((const float4*)p)[tid];
    float4 v1 = ((const float4*)p)[tid + 256];

    float m = fmaxf(fmaxf(fmaxf(v0.x, v0.y), fmaxf(v0.z, v0.w)),
                    fmaxf(fmaxf(v1.x, v1.y), fmaxf(v1.z, v1.w)));
    m = warpMax(m);
    if ((tid & 31) == 0) red[tid >> 5] = m;
    __syncthreads();
    m = red[0];
#pragma unroll
    for (int i = 1; i < 8; i++) m = fmaxf(m, red[i]);
    __syncthreads();   // everyone done reading red before reuse

    v0.x = expf(v0.x - m); v0.y = expf(v0.y - m);
    v0.z = expf(v0.z - m); v0.w = expf(v0.w - m);
    v1.x = expf(v1.x - m); v1.y = expf(v1.y - m);
    v1.z = expf(v1.z - m); v1.w = expf(v1.w - m);

    float s = (v0.x + v0.y + v0.z + v0.w) + (v1.x + v1.y + v1.z + v1.w);
    s = warpSum(s);
    if ((tid & 31) == 0) red[tid >> 5] = s;
    __syncthreads();
    s = red[0] + red[1] + red[2] + red[3] + red[4] + red[5] + red[6] + red[7];

    const float inv = 1.0f / s;
    v0.x *= inv; v0.y *= inv; v0.z *= inv; v0.w *= inv;
    v1.x *= inv; v1.y *= inv; v1.z *= inv; v1.w *= inv;

    ((float4*)p)[tid]       = v0;
    ((float4*)p)[tid + 256] = v1;
}

// ---------------------------------------------------------------------------
// Kernel 3: O[b,n,d] = sum_m P[b,n,m] * X[b,m,d].  NN GEMM, same tiling.
// ---------------------------------------------------------------------------
__global__ __launch_bounds__(256) void gemm_out(const float* __restrict__ X,
                                                float* __restrict__ out) {
    const int b = blockIdx.z;
    const int rowBase = blockIdx.y * 128;   // n
    const int colBase = blockIdx.x * 128;   // d
    const float* Pb = g_scratch + (size_t)b * GN * GN;
    const float* Xb = X + (size_t)b * GN * GD;

    __shared__ float As[16][128];
    __shared__ float Bs[16][128];

    float acc[8][8] = {};

    const int tid = threadIdx.x;
    const int tx = tid & 15;
    const int ty = tid >> 4;

    for (int m0 = 0; m0 < GN; m0 += 16) {
        // A tile: P[rowBase+row][m0+k], transposed store As[k][row]
#pragma unroll
        for (int l = 0; l < 2; l++) {
            int slot = tid + l * 256;
            int row  = slot >> 2;
            int k4   = (slot & 3) << 2;
            float4 va = *(const float4*)(Pb + (size_t)(rowBase + row) * GN + m0 + k4);
            As[k4 + 0][row] = va.x;
            As[k4 + 1][row] = va.y;
            As[k4 + 2][row] = va.z;
            As[k4 + 3][row] = va.w;
        }
        // B tile: X[m0+k][colBase+c], natural layout Bs[k][c]
#pragma unroll
        for (int l = 0; l < 2; l++) {
            int slot = tid + l * 256;
            int krow = slot >> 5;              // 0..15
            int c4   = (slot & 31) << 2;       // 0..124
            *(float4*)&Bs[krow][c4] =
                *(const float4*)(Xb + (size_t)(m0 + krow) * GD + colBase + c4);
        }
        __syncthreads();

#pragma unroll
        for (int k = 0; k < 16; k++) {
            float4 a0 = *(const float4*)&As[k][ty * 8];
            float4 a1 = *(const float4*)&As[k][ty * 8 + 4];
            float4 b0 = *(const float4*)&Bs[k][tx * 8];
            float4 b1 = *(const float4*)&Bs[k][tx * 8 + 4];
            float a[8] = {a0.x, a0.y, a0.z, a0.w, a1.x, a1.y, a1.z, a1.w};
            float bb[8] = {b0.x, b0.y, b0.z, b0.w, b1.x, b1.y, b1.z, b1.w};
#pragma unroll
            for (int i = 0; i < 8; i++)
#pragma unroll
                for (int j = 0; j < 8; j++)
                    acc[i][j] = fmaf(a[i], bb[j], acc[i][j]);
        }
        __syncthreads();
    }

    float* Ob = out + (size_t)b * GN * GD;
#pragma unroll
    for (int i = 0; i < 8; i++) {
        const int n = rowBase + ty * 8 + i;
        const int d0 = colBase + tx * 8;
        *(float4*)(Ob + (size_t)n * GD + d0) =
            make_float4(acc[i][0], acc[i][1], acc[i][2], acc[i][3]);
        *(float4*)(Ob + (size_t)n * GD + d0 + 4) =
            make_float4(acc[i][4], acc[i][5], acc[i][6], acc[i][7]);
    }
}

// ---------------------------------------------------------------------------
// Launch: inputs are [node_features(f32 B*N*D), nodes(i64, unused), adj(i32 B*N*N)]
// ---------------------------------------------------------------------------
extern "C" void kernel_launch(void* const* d_in, const int* in_sizes, int n_in,
                              void* d_out, int out_size) {
    const float* X   = (const float*)d_in[0];
    const int*   adj = (const int*)d_in[2];
    float*       out = (float*)d_out;

    dim3 g1(GN / 128, GN / 128, GB);          // 16 x 16 x 8
    gemm_scores<<<g1, 256>>>(X, adj);

    softmax_rows<<<GB * GN, 256>>>();          // 16384 rows

    dim3 g2(GD / 128, GN / 128, GB);          // 4 x 16 x 8
    gemm_out<<<g2, 256>>>(X, out);
}

// round 3
// speedup vs baseline: 2.2345x; 2.2345x over previous
#include <cuda_runtime.h>
#include <cuda_bf16.h>
#include <cstdint>

#define GN 2048
#define GD 512
#define GB 8
#define NEG_INF_F (-9999999.0f)

// ---------------- device scratch (no allocs allowed) ----------------
__device__ float          g_scratch[(size_t)GB * GN * GN];  // masked scores S (fp32)
__device__ __nv_bfloat16  g_phi[(size_t)GB * GN * GN];      // softmax probs hi
__device__ __nv_bfloat16  g_plo[(size_t)GB * GN * GN];      // softmax probs lo
__device__ __nv_bfloat16  g_xhi[(size_t)GB * GN * GD];      // X hi   [b,n,d]
__device__ __nv_bfloat16  g_xlo[(size_t)GB * GN * GD];      // X lo   [b,n,d]
__device__ __nv_bfloat16  g_xthi[(size_t)GB * GD * GN];     // X^T hi [b,d,n]
__device__ __nv_bfloat16  g_xtlo[(size_t)GB * GD * GN];     // X^T lo [b,d,n]

// ---------------- helpers ----------------
__device__ __forceinline__ uint32_t smem_u32(const void* p) {
    uint32_t a;
    asm("{ .reg .u64 t; cvta.to.shared.u64 t, %1; cvt.u32.u64 %0, t; }" : "=r"(a) : "l"(p));
    return a;
}

#define CP_ASYNC16(dst, src) \
    asm volatile("cp.async.cg.shared.global [%0], [%1], 16;" :: "r"(dst), "l"(src))
#define CP_COMMIT() asm volatile("cp.async.commit_group;" ::: "memory")
#define CP_WAIT2()  asm volatile("cp.async.wait_group 2;" ::: "memory")

__device__ __forceinline__ void ldsm4(uint32_t* r, uint32_t addr) {
    asm volatile("ldmatrix.sync.aligned.m8n8.x4.shared.b16 {%0,%1,%2,%3}, [%4];"
                 : "=r"(r[0]), "=r"(r[1]), "=r"(r[2]), "=r"(r[3]) : "r"(addr));
}

__device__ __forceinline__ void mma16816(float* c, const uint32_t* a, const uint32_t* b) {
    asm volatile(
        "mma.sync.aligned.m16n8k16.row.col.f32.bf16.bf16.f32 "
        "{%0,%1,%2,%3}, {%4,%5,%6,%7}, {%8,%9}, {%0,%1,%2,%3};"
        : "+f"(c[0]), "+f"(c[1]), "+f"(c[2]), "+f"(c[3])
        : "r"(a[0]), "r"(a[1]), "r"(a[2]), "r"(a[3]), "r"(b[0]), "r"(b[1]));
}

// ---------------- smem layout ----------------
// Per stream tile: 128 rows x 32 bf16, row stride 40 elems (80B) -> conflict-free ldmatrix.
#define ROW_B    80
#define STREAM_B (128 * ROW_B)        // 10240 B
#define STAGE_B  (4 * STREAM_B)       // Ahi, Alo, Bhi, Blo = 40960 B
#define NSTAGE   3
#define SMEM_BYTES (NSTAGE * STAGE_B) // 122880 B

// Load one 4-stream stage (k-chunk of 32) with cp.async. 256 threads.
__device__ __forceinline__ void load_stage(uint32_t smemStage,
                                           const __nv_bfloat16* a_hi,
                                           const __nv_bfloat16* a_lo, int ldA,
                                           const __nv_bfloat16* b_hi,
                                           const __nv_bfloat16* b_lo, int ldB,
                                           int k0) {
    const int t = threadIdx.x;
    const __nv_bfloat16* srcs[4] = {a_hi, a_lo, b_hi, b_lo};
    const int lds[4] = {ldA, ldA, ldB, ldB};
#pragma unroll
    for (int st = 0; st < 4; st++) {
#pragma unroll
        for (int rep = 0; rep < 2; rep++) {
            int c   = t + rep * 256;          // 0..511
            int row = c >> 2;                 // 0..127
            int k8  = c & 3;                  // 16B chunk within 32-elem row
            uint32_t d = smemStage + st * STREAM_B + row * ROW_B + k8 * 16;
            const __nv_bfloat16* s = srcs[st] + (size_t)row * lds[st] + k0 + k8 * 8;
            CP_ASYNC16(d, s);
        }
    }
}

// Core: acc[2][8][4] += A(128 x K) * B(128 x K)^T with bf16 hi/lo 3-term split.
// Warp layout: 4 (m) x 2 (n); warp tile 32 x 64.
__device__ __forceinline__ void gemm_core(uint32_t sb,
                                          const __nv_bfloat16* a_hi,
                                          const __nv_bfloat16* a_lo, int ldA,
                                          const __nv_bfloat16* b_hi,
                                          const __nv_bfloat16* b_lo, int ldB,
                                          int ksteps, float acc[2][8][4]) {
    const int l = threadIdx.x & 31;
    const int w = threadIdx.x >> 5;
    const int wm = (w & 3) * 32;
    const int wn = (w >> 2) * 64;

    // ldmatrix lane address components
    const int aRow = wm + (l & 15);
    const int aCb  = (l >> 4) * 16;
    const int bRow = wn + (l & 7) + ((l >> 4) & 1) * 8;
    const int bCb  = ((l >> 3) & 1) * 16;

    // prologue: stages 0, 1
    load_stage(sb, a_hi, a_lo, ldA, b_hi, b_lo, ldB, 0);
    CP_COMMIT();
    load_stage(sb + STAGE_B, a_hi, a_lo, ldA, b_hi, b_lo, ldB, 32);
    CP_COMMIT();

#pragma unroll 1
    for (int i = 0; i < ksteps; i++) {
        if (i + 2 < ksteps)
            load_stage(sb + ((i + 2) % NSTAGE) * STAGE_B,
                       a_hi, a_lo, ldA, b_hi, b_lo, ldB, (i + 2) * 32);
        CP_COMMIT();          // always commit -> constant wait depth
        CP_WAIT2();
        __syncthreads();

        const uint32_t stg = sb + (i % NSTAGE) * STAGE_B;
#pragma unroll
        for (int s = 0; s < 2; s++) {
            uint32_t ah[2][4], al[2][4];
#pragma unroll
            for (int mf = 0; mf < 2; mf++) {
                uint32_t ad = stg + (aRow + mf * 16) * ROW_B + s * 32 + aCb;
                ldsm4(ah[mf], ad);
                ldsm4(al[mf], ad + STREAM_B);
            }
            uint32_t bh[4][4], bl[4][4];
#pragma unroll
            for (int nq = 0; nq < 4; nq++) {
                uint32_t bd = stg + 2 * STREAM_B + (bRow + nq * 16) * ROW_B + s * 32 + bCb;
                ldsm4(bh[nq], bd);
                ldsm4(bl[nq], bd + STREAM_B);
            }
#pragma unroll
            for (int mf = 0; mf < 2; mf++)
#pragma unroll
                for (int nq = 0; nq < 4; nq++)
#pragma unroll
                    for (int h = 0; h < 2; h++) {
                        float* C = acc[mf][nq * 2 + h];
                        mma16816(C, ah[mf], &bh[nq][h * 2]);   // hi*hi
                        mma16816(C, ah[mf], &bl[nq][h * 2]);   // hi*lo
                        mma16816(C, al[mf], &bh[nq][h * 2]);   // lo*hi
                    }
        }
        __syncthreads();
    }
}

// ---------------------------------------------------------------------------
// Kernel 0: split X into bf16 hi/lo, plus transposed copies.
// ---------------------------------------------------------------------------
__global__ __launch_bounds__(256) void convert_split(const float* __restrict__ X) {
    __shared__ float tile[32][33];
    const int b  = blockIdx.z;
    const int d0 = blockIdx.x * 32;
    const int n0 = blockIdx.y * 32;
    const int tx = threadIdx.x & 31;
    const int ty = threadIdx.x >> 5;
    const float* Xb = X + (size_t)b * GN * GD;

#pragma unroll
    for (int k = 0; k < 4; k++) {
        int n = n0 + ty + k * 8;
        float v = Xb[(size_t)n * GD + d0 + tx];
        tile[ty + k * 8][tx] = v;
        __nv_bfloat16 h = __float2bfloat16(v);
        float lo = v - __bfloat162float(h);
        size_t idx = ((size_t)b * GN + n) * GD + d0 + tx;
        g_xhi[idx] = h;
        g_xlo[idx] = __float2bfloat16(lo);
    }
    __syncthreads();
#pragma unroll
    for (int k = 0; k < 4; k++) {
        int d = d0 + ty + k * 8;
        float v = tile[tx][ty + k * 8];
        __nv_bfloat16 h = __float2bfloat16(v);
        float lo = v - __bfloat162float(h);
        size_t idx = ((size_t)b * GD + d) * GN + n0 + tx;
        g_xthi[idx] = h;
        g_xtlo[idx] = __float2bfloat16(lo);
    }
}

// ---------------------------------------------------------------------------
// Kernel 1: S = X X^T masked by adj (+self) -> g_scratch (fp32).
// ---------------------------------------------------------------------------
__global__ __launch_bounds__(256) void gemm1_mma(const int* __restrict__ adj) {
    extern __shared__ char smem[];
    const uint32_t sb = smem_u32(smem);
    const int b = blockIdx.z;
    const int rowBase = blockIdx.y * 128;
    const int colBase = blockIdx.x * 128;

    float acc[2][8][4] = {};
    gemm_core(sb,
              g_xhi + ((size_t)b * GN + rowBase) * GD,
              g_xlo + ((size_t)b * GN + rowBase) * GD, GD,
              g_xhi + ((size_t)b * GN + colBase) * GD,
              g_xlo + ((size_t)b * GN + colBase) * GD, GD,
              GD / 32, acc);

    const int l = threadIdx.x & 31;
    const int w = threadIdx.x >> 5;
    const int wm = (w & 3) * 32;
    const int wn = (w >> 2) * 64;
    const int* adjb = adj + (size_t)b * GN * GN;
    float* Sb = g_scratch + (size_t)b * GN * GN;

#pragma unroll
    for (int mf = 0; mf < 2; mf++) {
        const int r0 = rowBase + wm + mf * 16 + (l >> 2);
        const int r1 = r0 + 8;
#pragma unroll
        for (int nf = 0; nf < 8; nf++) {
            const int c = colBase + wn + nf * 8 + (l & 3) * 2;
            int2 a0 = *(const int2*)(adjb + (size_t)r0 * GN + c);
            int2 a1 = *(const int2*)(adjb + (size_t)r1 * GN + c);
            float2 o0, o1;
            o0.x = (a0.x != 0 || r0 == c)     ? acc[mf][nf][0] : NEG_INF_F;
            o0.y = (a0.y != 0 || r0 == c + 1) ? acc[mf][nf][1] : NEG_INF_F;
            o1.x = (a1.x != 0 || r1 == c)     ? acc[mf][nf][2] : NEG_INF_F;
            o1.y = (a1.y != 0 || r1 == c + 1) ? acc[mf][nf][3] : NEG_INF_F;
            *(float2*)(Sb + (size_t)r0 * GN + c) = o0;
            *(float2*)(Sb + (size_t)r1 * GN + c) = o1;
        }
    }
}

// ---------------------------------------------------------------------------
// Kernel 2: row softmax over g_scratch -> bf16 hi/lo probs.
// ---------------------------------------------------------------------------
__device__ __forceinline__ float warpMax(float v) {
#pragma unroll
    for (int o = 16; o > 0; o >>= 1) v = fmaxf(v, __shfl_xor_sync(0xffffffffu, v, o));
    return v;
}
__device__ __forceinline__ float warpSum(float v) {
#pragma unroll
    for (int o = 16; o > 0; o >>= 1) v += __shfl_xor_sync(0xffffffffu, v, o);
    return v;
}
__device__ __forceinline__ void store_split4(__nv_bfloat16* ph, __nv_bfloat16* pl,
                                             int e4, float4 v) {
    __nv_bfloat16 h0 = __float2bfloat16(v.x), h1 = __float2bfloat16(v.y);
    __nv_bfloat16 h2 = __float2bfloat16(v.z), h3 = __float2bfloat16(v.w);
    __nv_bfloat162 H0; H0.x = h0; H0.y = h1;
    __nv_bfloat162 H1; H1.x = h2; H1.y = h3;
    __nv_bfloat162 L0, L1;
    L0.x = __float2bfloat16(v.x - __bfloat162float(h0));
    L0.y = __float2bfloat16(v.y - __bfloat162float(h1));
    L1.x = __float2bfloat16(v.z - __bfloat162float(h2));
    L1.y = __float2bfloat16(v.w - __bfloat162float(h3));
    ((__nv_bfloat162*)ph)[e4 * 2]     = H0;
    ((__nv_bfloat162*)ph)[e4 * 2 + 1] = H1;
    ((__nv_bfloat162*)pl)[e4 * 2]     = L0;
    ((__nv_bfloat162*)pl)[e4 * 2 + 1] = L1;
}

__global__ __launch_bounds__(256) void softmax_split() {
    __shared__ float red[8];
    const size_t row = blockIdx.x;
    const float* p = g_scratch + row * GN;
    const int tid = threadIdx.x;

    float4 v0 = ((const float4*)p)[tid];
    float4 v1 = ((const float4*)p)[tid + 256];

    float m = fmaxf(fmaxf(fmaxf(v0.x, v0.y), fmaxf(v0.z, v0.w)),
                    fmaxf(fmaxf(v1.x, v1.y), fmaxf(v1.z, v1.w)));
    m = warpMax(m);
    if ((tid & 31) == 0) red[tid >> 5] = m;
    __syncthreads();
    m = red[0];
#pragma unroll
    for (int i = 1; i < 8; i++) m = fmaxf(m, red[i]);
    __syncthreads();

    v0.x = expf(v0.x - m); v0.y = expf(v0.y - m);
    v0.z = expf(v0.z - m); v0.w = expf(v0.w - m);
    v1.x = expf(v1.x - m); v1.y = expf(v1.y - m);
    v1.z = expf(v1.z - m); v1.w = expf(v1.w - m);

    float s = (v0.x + v0.y + v0.z + v0.w) + (v1.x + v1.y + v1.z + v1.w);
    s = warpSum(s);
    if ((tid & 31) == 0) red[tid >> 5] = s;
    __syncthreads();
    s = red[0] + red[1] + red[2] + red[3] + red[4] + red[5] + red[6] + red[7];

    const float inv = 1.0f / s;
    v0.x *= inv; v0.y *= inv; v0.z *= inv; v0.w *= inv;
    v1.x *= inv; v1.y *= inv; v1.z *= inv; v1.w *= inv;

    __nv_bfloat16* ph = g_phi + row * GN;
    __nv_bfloat16* pl = g_plo + row * GN;
    store_split4(ph, pl, tid, v0);
    store_split4(ph, pl, tid + 256, v1);
}

// ---------------------------------------------------------------------------
// Kernel 3: O = P X. A = P (k = m contiguous), B = X^T (k = m contiguous).
// ---------------------------------------------------------------------------
__global__ __launch_bounds__(256) void gemm2_mma(float* __restrict__ out) {
    extern __shared__ char smem[];
    const uint32_t sb = smem_u32(smem);
    const int b = blockIdx.z;
    const int rowBase = blockIdx.y * 128;   // n
    const int colBase = blockIdx.x * 128;   // d

    float acc[2][8][4] = {};
    gemm_core(sb,
              g_phi  + ((size_t)b * GN + rowBase) * GN,
              g_plo  + ((size_t)b * GN + rowBase) * GN, GN,
              g_xthi + ((size_t)b * GD + colBase) * GN,
              g_xtlo + ((size_t)b * GD + colBase) * GN, GN,
              GN / 32, acc);

    const int l = threadIdx.x & 31;
    const int w = threadIdx.x >> 5;
    const int wm = (w & 3) * 32;
    const int wn = (w >> 2) * 64;
    float* Ob = out + (size_t)b * GN * GD;

#pragma unroll
    for (int mf = 0; mf < 2; mf++) {
        const int r0 = rowBase + wm + mf * 16 + (l >> 2);
        const int r1 = r0 + 8;
#pragma unroll
        for (int nf = 0; nf < 8; nf++) {
            const int c = colBase + wn + nf * 8 + (l & 3) * 2;
            *(float2*)(Ob + (size_t)r0 * GD + c) =
                make_float2(acc[mf][nf][0], acc[mf][nf][1]);
            *(float2*)(Ob + (size_t)r1 * GD + c) =
                make_float2(acc[mf][nf][2], acc[mf][nf][3]);
        }
    }
}

// ---------------------------------------------------------------------------
extern "C" void kernel_launch(void* const* d_in, const int* in_sizes, int n_in,
                              void* d_out, int out_size) {
    const float* X   = (const float*)d_in[0];
    const int*   adj = (const int*)d_in[2];
    float*       out = (float*)d_out;

    static bool attrDone = false;
    if (!attrDone) {
        cudaFuncSetAttribute(gemm1_mma, cudaFuncAttributeMaxDynamicSharedMemorySize, SMEM_BYTES);
        cudaFuncSetAttribute(gemm2_mma, cudaFuncAttributeMaxDynamicSharedMemorySize, SMEM_BYTES);
        attrDone = true;
    }

    convert_split<<<dim3(GD / 32, GN / 32, GB), 256>>>(X);
    gemm1_mma<<<dim3(GN / 128, GN / 128, GB), 256, SMEM_BYTES>>>(adj);
    softmax_split<<<GB * GN, 256>>>();
    gemm2_mma<<<dim3(GD / 128, GN / 128, GB), 256, SMEM_BYTES>>>(out);
}

// round 4
// speedup vs baseline: 2.7104x; 1.2130x over previous
#include <cuda_runtime.h>
#include <cuda_bf16.h>
#include <cstdint>

#define GN 2048
#define GD 512
#define GB 8
#define NEG_INF_F (-9999999.0f)

// ---------------- device scratch (no allocs allowed) ----------------
__device__ float          g_scratch[(size_t)GB * GN * GN];  // masked scores S (fp32)
__device__ __nv_bfloat16  g_phi[(size_t)GB * GN * GN];      // softmax probs hi
__device__ __nv_bfloat16  g_plo[(size_t)GB * GN * GN];      // softmax probs lo
__device__ __nv_bfloat16  g_xhi[(size_t)GB * GN * GD];      // X hi   [b,n,d]
__device__ __nv_bfloat16  g_xlo[(size_t)GB * GN * GD];      // X lo   [b,n,d]
__device__ __nv_bfloat16  g_xthi[(size_t)GB * GD * GN];     // X^T hi [b,d,n]
__device__ __nv_bfloat16  g_xtlo[(size_t)GB * GD * GN];     // X^T lo [b,d,n]

// ---------------- helpers ----------------
__device__ __forceinline__ uint32_t smem_u32(const void* p) {
    uint32_t a;
    asm("{ .reg .u64 t; cvta.to.shared.u64 t, %1; cvt.u32.u64 %0, t; }" : "=r"(a) : "l"(p));
    return a;
}

#define CP_ASYNC16(dst, src) \
    asm volatile("cp.async.cg.shared.global [%0], [%1], 16;" :: "r"(dst), "l"(src))
#define CP_COMMIT() asm volatile("cp.async.commit_group;" ::: "memory")
#define CP_WAIT1()  asm volatile("cp.async.wait_group 1;" ::: "memory")
#define CP_WAIT0()  asm volatile("cp.async.wait_group 0;" ::: "memory")

__device__ __forceinline__ void ldsm4(uint32_t* r, uint32_t addr) {
    asm volatile("ldmatrix.sync.aligned.m8n8.x4.shared.b16 {%0,%1,%2,%3}, [%4];"
                 : "=r"(r[0]), "=r"(r[1]), "=r"(r[2]), "=r"(r[3]) : "r"(addr));
}

__device__ __forceinline__ void mma16816(float* c, const uint32_t* a, const uint32_t* b) {
    asm volatile(
        "mma.sync.aligned.m16n8k16.row.col.f32.bf16.bf16.f32 "
        "{%0,%1,%2,%3}, {%4,%5,%6,%7}, {%8,%9}, {%0,%1,%2,%3};"
        : "+f"(c[0]), "+f"(c[1]), "+f"(c[2]), "+f"(c[3])
        : "r"(a[0]), "r"(a[1]), "r"(a[2]), "r"(a[3]), "r"(b[0]), "r"(b[1]));
}

// ---------------- smem layout ----------------
// Per stream tile: 128 rows x 32 bf16, row stride 40 elems (80B) -> conflict-free ldmatrix.
#define ROW_B    80
#define STREAM_B (128 * ROW_B)        // 10240 B
#define STAGE_B  (4 * STREAM_B)       // Ahi, Alo, Bhi, Blo = 40960 B
#define NSTAGE   2
#define SMEM_BYTES (NSTAGE * STAGE_B) // 81920 B  -> 2 CTAs / SM

// Load one 4-stream stage (k-chunk of 32) with cp.async. 256 threads.
__device__ __forceinline__ void load_stage(uint32_t smemStage,
                                           const __nv_bfloat16* a_hi,
                                           const __nv_bfloat16* a_lo, int ldA,
                                           const __nv_bfloat16* b_hi,
                                           const __nv_bfloat16* b_lo, int ldB,
                                           int k0) {
    const int t = threadIdx.x;
    const __nv_bfloat16* srcs[4] = {a_hi, a_lo, b_hi, b_lo};
    const int lds[4] = {ldA, ldA, ldB, ldB};
#pragma unroll
    for (int st = 0; st < 4; st++) {
#pragma unroll
        for (int rep = 0; rep < 2; rep++) {
            int c   = t + rep * 256;          // 0..511
            int row = c >> 2;                 // 0..127
            int k8  = c & 3;                  // 16B chunk within 32-elem row
            uint32_t d = smemStage + st * STREAM_B + row * ROW_B + k8 * 16;
            const __nv_bfloat16* s = srcs[st] + (size_t)row * lds[st] + k0 + k8 * 8;
            CP_ASYNC16(d, s);
        }
    }
}

// Core: acc[2][8][4] += A(128 x K) * B(128 x K)^T with bf16 hi/lo 3-term split.
// Warp layout: 4 (m) x 2 (n); warp tile 32 x 64. Double-buffered cp.async.
__device__ __forceinline__ void gemm_core(uint32_t sb,
                                          const __nv_bfloat16* a_hi,
                                          const __nv_bfloat16* a_lo, int ldA,
                                          const __nv_bfloat16* b_hi,
                                          const __nv_bfloat16* b_lo, int ldB,
                                          int ksteps, float acc[2][8][4]) {
    const int l = threadIdx.x & 31;
    const int w = threadIdx.x >> 5;
    const int wm = (w & 3) * 32;
    const int wn = (w >> 2) * 64;

    // ldmatrix lane address components
    const int aRow = wm + (l & 15);
    const int aCb  = (l >> 4) * 16;
    const int bRow = wn + (l & 7) + ((l >> 4) & 1) * 8;
    const int bCb  = ((l >> 3) & 1) * 16;

    // prologue: stage 0
    load_stage(sb, a_hi, a_lo, ldA, b_hi, b_lo, ldB, 0);
    CP_COMMIT();

#pragma unroll 1
    for (int i = 0; i < ksteps; i++) {
        if (i + 1 < ksteps) {
            load_stage(sb + ((i + 1) & 1) * STAGE_B,
                       a_hi, a_lo, ldA, b_hi, b_lo, ldB, (i + 1) * 32);
            CP_COMMIT();
            CP_WAIT1();        // stage i complete, stage i+1 in flight
        } else {
            CP_WAIT0();        // final stage complete
        }
        __syncthreads();

        const uint32_t stg = sb + (i & 1) * STAGE_B;
#pragma unroll
        for (int s = 0; s < 2; s++) {
            uint32_t ah[2][4], al[2][4];
#pragma unroll
            for (int mf = 0; mf < 2; mf++) {
                uint32_t ad = stg + (aRow + mf * 16) * ROW_B + s * 32 + aCb;
                ldsm4(ah[mf], ad);
                ldsm4(al[mf], ad + STREAM_B);
            }
            uint32_t bh[4][4], bl[4][4];
#pragma unroll
            for (int nq = 0; nq < 4; nq++) {
                uint32_t bd = stg + 2 * STREAM_B + (bRow + nq * 16) * ROW_B + s * 32 + bCb;
                ldsm4(bh[nq], bd);
                ldsm4(bl[nq], bd + STREAM_B);
            }
#pragma unroll
            for (int mf = 0; mf < 2; mf++)
#pragma unroll
                for (int nq = 0; nq < 4; nq++)
#pragma unroll
                    for (int h = 0; h < 2; h++) {
                        float* C = acc[mf][nq * 2 + h];
                        mma16816(C, ah[mf], &bh[nq][h * 2]);   // hi*hi
                        mma16816(C, ah[mf], &bl[nq][h * 2]);   // hi*lo
                        mma16816(C, al[mf], &bh[nq][h * 2]);   // lo*hi
                    }
        }
        __syncthreads();   // all reads of buf (i&1) done before iter i+1 reload
    }
}

// ---------------------------------------------------------------------------
// Kernel 0: split X into bf16 hi/lo, plus transposed copies.
// ---------------------------------------------------------------------------
__global__ __launch_bounds__(256) void convert_split(const float* __restrict__ X) {
    __shared__ float tile[32][33];
    const int b  = blockIdx.z;
    const int d0 = blockIdx.x * 32;
    const int n0 = blockIdx.y * 32;
    const int tx = threadIdx.x & 31;
    const int ty = threadIdx.x >> 5;
    const float* Xb = X + (size_t)b * GN * GD;

#pragma unroll
    for (int k = 0; k < 4; k++) {
        int n = n0 + ty + k * 8;
        float v = Xb[(size_t)n * GD + d0 + tx];
        tile[ty + k * 8][tx] = v;
        __nv_bfloat16 h = __float2bfloat16(v);
        float lo = v - __bfloat162float(h);
        size_t idx = ((size_t)b * GN + n) * GD + d0 + tx;
        g_xhi[idx] = h;
        g_xlo[idx] = __float2bfloat16(lo);
    }
    __syncthreads();
#pragma unroll
    for (int k = 0; k < 4; k++) {
        int d = d0 + ty + k * 8;
        float v = tile[tx][ty + k * 8];
        __nv_bfloat16 h = __float2bfloat16(v);
        float lo = v - __bfloat162float(h);
        size_t idx = ((size_t)b * GD + d) * GN + n0 + tx;
        g_xthi[idx] = h;
        g_xtlo[idx] = __float2bfloat16(lo);
    }
}

// ---------------------------------------------------------------------------
// Kernel 1: S = X X^T masked by adj (+self) -> g_scratch (fp32).
// ---------------------------------------------------------------------------
__global__ __launch_bounds__(256, 2) void gemm1_mma(const int* __restrict__ adj) {
    extern __shared__ char smem[];
    const uint32_t sb = smem_u32(smem);
    const int b = blockIdx.z;
    const int rowBase = blockIdx.y * 128;
    const int colBase = blockIdx.x * 128;

    float acc[2][8][4] = {};
    gemm_core(sb,
              g_xhi + ((size_t)b * GN + rowBase) * GD,
              g_xlo + ((size_t)b * GN + rowBase) * GD, GD,
              g_xhi + ((size_t)b * GN + colBase) * GD,
              g_xlo + ((size_t)b * GN + colBase) * GD, GD,
              GD / 32, acc);

    const int l = threadIdx.x & 31;
    const int w = threadIdx.x >> 5;
    const int wm = (w & 3) * 32;
    const int wn = (w >> 2) * 64;
    const int* adjb = adj + (size_t)b * GN * GN;
    float* Sb = g_scratch + (size_t)b * GN * GN;

#pragma unroll
    for (int mf = 0; mf < 2; mf++) {
        const int r0 = rowBase + wm + mf * 16 + (l >> 2);
        const int r1 = r0 + 8;
#pragma unroll
        for (int nf = 0; nf < 8; nf++) {
            const int c = colBase + wn + nf * 8 + (l & 3) * 2;
            int2 a0 = *(const int2*)(adjb + (size_t)r0 * GN + c);
            int2 a1 = *(const int2*)(adjb + (size_t)r1 * GN + c);
            float2 o0, o1;
            o0.x = (a0.x != 0 || r0 == c)     ? acc[mf][nf][0] : NEG_INF_F;
            o0.y = (a0.y != 0 || r0 == c + 1) ? acc[mf][nf][1] : NEG_INF_F;
            o1.x = (a1.x != 0 || r1 == c)     ? acc[mf][nf][2] : NEG_INF_F;
            o1.y = (a1.y != 0 || r1 == c + 1) ? acc[mf][nf][3] : NEG_INF_F;
            *(float2*)(Sb + (size_t)r0 * GN + c) = o0;
            *(float2*)(Sb + (size_t)r1 * GN + c) = o1;
        }
    }
}

// ---------------------------------------------------------------------------
// Kernel 2: row softmax over g_scratch -> bf16 hi/lo probs.
// ---------------------------------------------------------------------------
__device__ __forceinline__ float warpMax(float v) {
#pragma unroll
    for (int o = 16; o > 0; o >>= 1) v = fmaxf(v, __shfl_xor_sync(0xffffffffu, v, o));
    return v;
}
__device__ __forceinline__ float warpSum(float v) {
#pragma unroll
    for (int o = 16; o > 0; o >>= 1) v += __shfl_xor_sync(0xffffffffu, v, o);
    return v;
}
__device__ __forceinline__ void store_split4(__nv_bfloat16* ph, __nv_bfloat16* pl,
                                             int e4, float4 v) {
    __nv_bfloat16 h0 = __float2bfloat16(v.x), h1 = __float2bfloat16(v.y);
    __nv_bfloat16 h2 = __float2bfloat16(v.z), h3 = __float2bfloat16(v.w);
    __nv_bfloat162 H0; H0.x = h0; H0.y = h1;
    __nv_bfloat162 H1; H1.x = h2; H1.y = h3;
    __nv_bfloat162 L0, L1;
    L0.x = __float2bfloat16(v.x - __bfloat162float(h0));
    L0.y = __float2bfloat16(v.y - __bfloat162float(h1));
    L1.x = __float2bfloat16(v.z - __bfloat162float(h2));
    L1.y = __float2bfloat16(v.w - __bfloat162float(h3));
    ((__nv_bfloat162*)ph)[e4 * 2]     = H0;
    ((__nv_bfloat162*)ph)[e4 * 2 + 1] = H1;
    ((__nv_bfloat162*)pl)[e4 * 2]     = L0;
    ((__nv_bfloat162*)pl)[e4 * 2 + 1] = L1;
}

__global__ __launch_bounds__(256) void softmax_split() {
    __shared__ float red[8];
    const size_t row = blockIdx.x;
    const float* p = g_scratch + row * GN;
    const int tid = threadIdx.x;

    float4 v0 = ((const float4*)p)[tid];
    float4 v1 = ((const float4*)p)[tid + 256];

    float m = fmaxf(fmaxf(fmaxf(v0.x, v0.y), fmaxf(v0.z, v0.w)),
                    fmaxf(fmaxf(v1.x, v1.y), fmaxf(v1.z, v1.w)));
    m = warpMax(m);
    if ((tid & 31) == 0) red[tid >> 5] = m;
    __syncthreads();
    m = red[0];
#pragma unroll
    for (int i = 1; i < 8; i++) m = fmaxf(m, red[i]);
    __syncthreads();

    v0.x = expf(v0.x - m); v0.y = expf(v0.y - m);
    v0.z = expf(v0.z - m); v0.w = expf(v0.w - m);
    v1.x = expf(v1.x - m); v1.y = expf(v1.y - m);
    v1.z = expf(v1.z - m); v1.w = expf(v1.w - m);

    float s = (v0.x + v0.y + v0.z + v0.w) + (v1.x + v1.y + v1.z + v1.w);
    s = warpSum(s);
    if ((tid & 31) == 0) red[tid >> 5] = s;
    __syncthreads();
    s = red[0] + red[1] + red[2] + red[3] + red[4] + red[5] + red[6] + red[7];

    const float inv = 1.0f / s;
    v0.x *= inv; v0.y *= inv; v0.z *= inv; v0.w *= inv;
    v1.x *= inv; v1.y *= inv; v1.z *= inv; v1.w *= inv;

    __nv_bfloat16* ph = g_phi + row * GN;
    __nv_bfloat16* pl = g_plo + row * GN;
    store_split4(ph, pl, tid, v0);
    store_split4(ph, pl, tid + 256, v1);
}

// ---------------------------------------------------------------------------
// Kernel 3: O = P X. A = P (k = m contiguous), B = X^T (k = m contiguous).
// ---------------------------------------------------------------------------
__global__ __launch_bounds__(256, 2) void gemm2_mma(float* __restrict__ out) {
    extern __shared__ char smem[];
    const uint32_t sb = smem_u32(smem);
    const int b = blockIdx.z;
    const int rowBase = blockIdx.y * 128;   // n
    const int colBase = blockIdx.x * 128;   // d

    float acc[2][8][4] = {};
    gemm_core(sb,
              g_phi  + ((size_t)b * GN + rowBase) * GN,
              g_plo  + ((size_t)b * GN + rowBase) * GN, GN,
              g_xthi + ((size_t)b * GD + colBase) * GN,
              g_xtlo + ((size_t)b * GD + colBase) * GN, GN,
              GN / 32, acc);

    const int l = threadIdx.x & 31;
    const int w = threadIdx.x >> 5;
    const int wm = (w & 3) * 32;
    const int wn = (w >> 2) * 64;
    float* Ob = out + (size_t)b * GN * GD;

#pragma unroll
    for (int mf = 0; mf < 2; mf++) {
        const int r0 = rowBase + wm + mf * 16 + (l >> 2);
        const int r1 = r0 + 8;
#pragma unroll
        for (int nf = 0; nf < 8; nf++) {
            const int c = colBase + wn + nf * 8 + (l & 3) * 2;
            *(float2*)(Ob + (size_t)r0 * GD + c) =
                make_float2(acc[mf][nf][0], acc[mf][nf][1]);
            *(float2*)(Ob + (size_t)r1 * GD + c) =
                make_float2(acc[mf][nf][2], acc[mf][nf][3]);
        }
    }
}

// ---------------------------------------------------------------------------
extern "C" void kernel_launch(void* const* d_in, const int* in_sizes, int n_in,
                              void* d_out, int out_size) {
    const float* X   = (const float*)d_in[0];
    const int*   adj = (const int*)d_in[2];
    float*       out = (float*)d_out;

    static bool attrDone = false;
    if (!attrDone) {
        cudaFuncSetAttribute(gemm1_mma, cudaFuncAttributeMaxDynamicSharedMemorySize, SMEM_BYTES);
        cudaFuncSetAttribute(gemm2_mma, cudaFuncAttributeMaxDynamicSharedMemorySize, SMEM_BYTES);
        attrDone = true;
    }

    convert_split<<<dim3(GD / 32, GN / 32, GB), 256>>>(X);
    gemm1_mma<<<dim3(GN / 128, GN / 128, GB), 256, SMEM_BYTES>>>(adj);
    softmax_split<<<GB * GN, 256>>>();
    gemm2_mma<<<dim3(GD / 128, GN / 128, GB), 256, SMEM_BYTES>>>(out);
}